// round 1
// baseline (speedup 1.0000x reference)
#include <cuda_runtime.h>

// Problem constants (fixed by the reference): B=8192, T=16, M=16, V=256
#define T_DIM 16
#define M_DIM 16
#define V_DIM 256
#define INS_DEL 10.0f
#define FIRST_CHAR_COST 10.0f

#define WARPS_PER_BLOCK 4
#define THREADS_PER_BLOCK (WARPS_PER_BLOCK * 32)

// Shared layout per warp (floats):
//   E[t][v]: exp(logits), row stride 260 (pad for bank behavior + 16B align)
//   S[t][m]: sub values, row stride 18 (conflict-free wavefront reads)
#define ESTRIDE 260
#define EWORDS (16 * ESTRIDE)      // 4160
#define SSTRIDE 18
#define SWORDS (16 * SSTRIDE)      // 288
#define WARP_SMEM_FLOATS 4480      // 4160 + 288 + pad, 16B-divisible
#define SMEM_BYTES (WARPS_PER_BLOCK * WARP_SMEM_FLOATS * 4)

__global__ void __launch_bounds__(THREADS_PER_BLOCK)
rhyme_dp_kernel(const float* __restrict__ logits,
                const int* __restrict__ tgt,
                const float* __restrict__ phon,
                float* __restrict__ out, int B)
{
    extern __shared__ float smem[];
    const int w    = threadIdx.x >> 5;
    const int lane = threadIdx.x & 31;
    const int b    = blockIdx.x * WARPS_PER_BLOCK + w;
    if (b >= B) return;

    float* E = smem + w * WARP_SMEM_FLOATS;
    float* S = E + EWORDS;

    const float* lg = logits + (size_t)b * (T_DIM * V_DIM);

    const int m  = lane & 15;   // output column / target index
    const int kh = lane >> 4;   // k-half (v in [0,128) or [128,256))

    // target char for this lane's m (both halves load the same, coalesced)
    const int gm = tgt[b * M_DIM + m];
    const int g0 = __shfl_sync(0xffffffffu, gm, 0);

    // ---------------- Phase 1: softmax numerators -> shared E, keep 1/Z ----
    float invZ[16];
#pragma unroll
    for (int t = 0; t < 16; ++t) {
        const float4* row = (const float4*)(lg + t * V_DIM);
        float4 x0 = row[lane * 2];
        float4 x1 = row[lane * 2 + 1];
        float4 e0, e1;
        e0.x = __expf(x0.x); e0.y = __expf(x0.y);
        e0.z = __expf(x0.z); e0.w = __expf(x0.w);
        e1.x = __expf(x1.x); e1.y = __expf(x1.y);
        e1.z = __expf(x1.z); e1.w = __expf(x1.w);
        float s = (e0.x + e0.y) + (e0.z + e0.w)
                + (e1.x + e1.y) + (e1.z + e1.w);
        float4* erow = (float4*)(E + t * ESTRIDE);
        erow[lane * 2]     = e0;
        erow[lane * 2 + 1] = e1;
#pragma unroll
        for (int o = 16; o; o >>= 1)
            s += __shfl_xor_sync(0xffffffffu, s, o);
        invZ[t] = __fdividef(1.0f, s);
    }
    __syncwarp();

    // ---------------- Phase 2: einsum sub[t][m] = sum_v p[t][v]*C[g_m][v] --
    // phon_cost is symmetric by construction -> use contiguous row g_m.
    const float* crow = phon + gm * V_DIM + kh * 128;
    float acc[16];
#pragma unroll
    for (int t = 0; t < 16; ++t) acc[t] = 0.0f;

#pragma unroll
    for (int q = 0; q < 16; ++q) {
        // rotate half-1's v-block order by one octet: its shared-E granule
        // lands in disjoint banks from half-0's -> conflict-free broadcast
        const int vq = kh ? ((q + 1) & 15) : q;
        const int vv = vq * 8;
        const float4 c0 = __ldg((const float4*)(crow + vv));
        const float4 c1 = __ldg((const float4*)(crow + vv + 4));
        const float* eb = E + kh * 128 + vv;
#pragma unroll
        for (int t = 0; t < 16; ++t) {
            const float4 e0 = *(const float4*)(eb + t * ESTRIDE);
            const float4 e1 = *(const float4*)(eb + t * ESTRIDE + 4);
            acc[t] += e0.x * c0.x + e0.y * c0.y + e0.z * c0.z + e0.w * c0.w
                    + e1.x * c1.x + e1.y * c1.y + e1.z * c1.z + e1.w * c1.w;
        }
    }
    // combine the two k-halves
#pragma unroll
    for (int t = 0; t < 16; ++t)
        acc[t] += __shfl_xor_sync(0xffffffffu, acc[t], 16);

    if (kh == 0) {
#pragma unroll
        for (int t = 0; t < 16; ++t)
            S[t * SSTRIDE + m] = acc[t] * invZ[t];
    }
    __syncwarp();

    // ---------------- Phase 3: soft-DP wavefront (lane = column j-1) ------
    // cell(i,j): softmin3(up+10, left+10, diag+sub[i-1][j-1]), i,j in 1..16
    float cur = 0.0f, prev = 0.0f;
#pragma unroll
    for (int s = 0; s <= 30; ++s) {
        float leftv = __shfl_up_sync(0xffffffffu, cur, 1);
        float diagv = __shfl_up_sync(0xffffffffu, prev, 1);
        const int i = s - m + 1;
        const bool active = (i >= 1) && (i <= 16);

        float up;
        if (i == 1) {                 // row above is DP row 0: 10*j
            up    = INS_DEL * (float)(m + 1);
            diagv = INS_DEL * (float)m;
        } else {
            up = cur;
        }
        if (m == 0) {                 // column left is DP col 0: 10*i
            leftv = INS_DEL * (float)i;
            diagv = INS_DEL * (float)(i - 1);
        }

        const int si = active ? (s - m) : 0;
        const float sc = S[si * SSTRIDE + m];

        const float a  = up    + INS_DEL;
        const float bb = leftv + INS_DEL;
        const float c  = diagv + sc;
        const float mn = fminf(a, fminf(bb, c));
        const float r  = __expf(mn - a) + __expf(mn - bb) + __expf(mn - c);
        const float val = mn - __logf(r);

        if (active) { prev = cur; cur = val; }
    }

    // ---------------- Phase 4: first-char term + output --------------------
    if (lane == 15) {
        const float fm = E[g0] * invZ[0];        // p[b,0,tgt[b,0]]
        out[b] = cur + FIRST_CHAR_COST * (1.0f - fm);
    }
}

extern "C" void kernel_launch(void* const* d_in, const int* in_sizes, int n_in,
                              void* d_out, int out_size)
{
    const float* logits = (const float*)d_in[0];   // tail_logits (B,T,V) f32
    const int*   tgt    = (const int*)  d_in[1];   // target_idx  (B,M) i32
    const float* phon   = (const float*)d_in[2];   // phon_cost   (V,V) f32
    float* out = (float*)d_out;
    const int B = out_size;                        // 8192

    cudaFuncSetAttribute(rhyme_dp_kernel,
                         cudaFuncAttributeMaxDynamicSharedMemorySize,
                         SMEM_BYTES);
    const int grid = (B + WARPS_PER_BLOCK - 1) / WARPS_PER_BLOCK;
    rhyme_dp_kernel<<<grid, THREADS_PER_BLOCK, SMEM_BYTES>>>(
        logits, tgt, phon, out, B);
}

// round 2
// speedup vs baseline: 1.2632x; 1.2632x over previous
#include <cuda_runtime.h>
#include <cuda_fp16.h>

// Problem constants (fixed by the reference): B=8192, T=16, M=16, V=256
#define T_DIM 16
#define M_DIM 16
#define V_DIM 256
#define INS_DEL 10.0f
#define FIRST_CHAR_COST 10.0f

#define WARPS_PER_BLOCK 4
#define THREADS_PER_BLOCK (WARPS_PER_BLOCK * 32)

// Per-warp shared layout:
//   P[t][v]   : softmax probs as half, row stride 256 halves (512B) -> 4096 halves
//   S[t][m]   : sub values fp32, row stride 18
#define P_HALVES (16 * 256)             // 4096 halves = 8192 B = 2048 floats
#define SSTRIDE 18
#define SWORDS (16 * SSTRIDE)           // 288 floats
#define WARP_SMEM_FLOATS (2048 + SWORDS + 16)   // 2352 floats = 9408 B
#define SMEM_BYTES (WARPS_PER_BLOCK * WARP_SMEM_FLOATS * 4)

__global__ void __launch_bounds__(THREADS_PER_BLOCK, 6)
rhyme_dp_kernel(const float* __restrict__ logits,
                const int* __restrict__ tgt,
                const float* __restrict__ phon,
                float* __restrict__ out, int B)
{
    extern __shared__ float smem[];
    const int w    = threadIdx.x >> 5;
    const int lane = threadIdx.x & 31;
    const int b    = blockIdx.x * WARPS_PER_BLOCK + w;
    if (b >= B) return;

    float* warp_base = smem + w * WARP_SMEM_FLOATS;
    __half* P = (__half*)warp_base;             // 4096 halves
    float*  S = warp_base + 2048;               // 288 floats

    const float* lg = logits + (size_t)b * (T_DIM * V_DIM);

    const int m  = lane & 15;   // output column / target index
    const int kh = lane >> 4;   // k-half (v in [0,128) or [128,256))

    const int gm = tgt[b * M_DIM + m];
    const int g0 = __shfl_sync(0xffffffffu, gm, 0);

    // ---------------- Phase 1: softmax -> shared P (half, invZ folded) -----
#pragma unroll
    for (int t = 0; t < 16; ++t) {
        const float4* row = (const float4*)(lg + t * V_DIM);
        float4 x0 = row[lane * 2];
        float4 x1 = row[lane * 2 + 1];
        float4 e0, e1;
        e0.x = __expf(x0.x); e0.y = __expf(x0.y);
        e0.z = __expf(x0.z); e0.w = __expf(x0.w);
        e1.x = __expf(x1.x); e1.y = __expf(x1.y);
        e1.z = __expf(x1.z); e1.w = __expf(x1.w);
        float s = (e0.x + e0.y) + (e0.z + e0.w)
                + (e1.x + e1.y) + (e1.z + e1.w);
#pragma unroll
        for (int o = 16; o; o >>= 1)
            s += __shfl_xor_sync(0xffffffffu, s, o);
        const float invZ = __fdividef(1.0f, s);

        __half2 h[4];
        h[0] = __floats2half2_rn(e0.x * invZ, e0.y * invZ);
        h[1] = __floats2half2_rn(e0.z * invZ, e0.w * invZ);
        h[2] = __floats2half2_rn(e1.x * invZ, e1.y * invZ);
        h[3] = __floats2half2_rn(e1.z * invZ, e1.w * invZ);
        // store 8 halves (16B) at half-index t*256 + lane*8
        *(uint4*)(P + t * 256 + lane * 8) = *(uint4*)h;
    }
    __syncwarp();

    // ---------------- Phase 2: sub[t][m] = sum_v p[t][v]*C[g_m][v] ---------
    // phon_cost symmetric -> contiguous row g_m. lane = (m, k-half).
    const float* crow = phon + gm * V_DIM + kh * 128;

    __half2 accA[16], accB[16];
    const __half2 hz = __float2half2_rn(0.0f);
#pragma unroll
    for (int t = 0; t < 16; ++t) { accA[t] = hz; accB[t] = hz; }

#pragma unroll
    for (int q = 0; q < 16; ++q) {
        // rotate half-1's v-octet order so its 16B granule is bank-disjoint
        // from half-0's within each broadcast LDS
        const int vq = kh ? ((q + 1) & 15) : q;
        const int vv = vq * 8;
        const float4 c0 = __ldg((const float4*)(crow + vv));
        const float4 c1 = __ldg((const float4*)(crow + vv + 4));
        __half2 ch0 = __floats2half2_rn(c0.x, c0.y);
        __half2 ch1 = __floats2half2_rn(c0.z, c0.w);
        __half2 ch2 = __floats2half2_rn(c1.x, c1.y);
        __half2 ch3 = __floats2half2_rn(c1.z, c1.w);
        const __half* pb = P + kh * 128 + vv;
#pragma unroll
        for (int t = 0; t < 16; ++t) {
            uint4 raw = *(const uint4*)(pb + t * 256);
            __half2 p0 = *(__half2*)&raw.x;
            __half2 p1 = *(__half2*)&raw.y;
            __half2 p2 = *(__half2*)&raw.z;
            __half2 p3 = *(__half2*)&raw.w;
            accA[t] = __hfma2(p0, ch0, accA[t]);
            accA[t] = __hfma2(p1, ch1, accA[t]);
            accB[t] = __hfma2(p2, ch2, accB[t]);
            accB[t] = __hfma2(p3, ch3, accB[t]);
        }
    }

    // combine accumulators (fp32) and the two k-halves
    if (1) {
#pragma unroll
        for (int t = 0; t < 16; ++t) {
            float2 fa = __half22float2(accA[t]);
            float2 fb = __half22float2(accB[t]);
            float v = (fa.x + fa.y) + (fb.x + fb.y);
            v += __shfl_xor_sync(0xffffffffu, v, 16);
            if (kh == 0) S[t * SSTRIDE + m] = v;
        }
    }
    __syncwarp();

    // ---------------- Phase 3: soft-DP wavefront (lane = column j-1) ------
    float cur = 0.0f, prev = 0.0f;
#pragma unroll
    for (int s = 0; s <= 30; ++s) {
        float leftv = __shfl_up_sync(0xffffffffu, cur, 1);
        float diagv = __shfl_up_sync(0xffffffffu, prev, 1);
        const int i = s - m + 1;
        const bool active = (i >= 1) && (i <= 16);

        float up;
        if (i == 1) {                 // row above is DP row 0: 10*j
            up    = INS_DEL * (float)(m + 1);
            diagv = INS_DEL * (float)m;
        } else {
            up = cur;
        }
        if (m == 0) {                 // column left is DP col 0: 10*i
            leftv = INS_DEL * (float)i;
            diagv = INS_DEL * (float)(i - 1);
        }

        const int si = active ? (s - m) : 0;
        const float sc = S[si * SSTRIDE + m];

        const float a  = up    + INS_DEL;
        const float bb = leftv + INS_DEL;
        const float c  = diagv + sc;
        const float mn = fminf(a, fminf(bb, c));
        const float r  = __expf(mn - a) + __expf(mn - bb) + __expf(mn - c);
        const float val = mn - __logf(r);

        if (active) { prev = cur; cur = val; }
    }

    // ---------------- Phase 4: first-char term + output --------------------
    if (lane == 15) {
        const float fm = __half2float(P[g0]);    // p[b,0,tgt[b,0]]
        out[b] = cur + FIRST_CHAR_COST * (1.0f - fm);
    }
}

extern "C" void kernel_launch(void* const* d_in, const int* in_sizes, int n_in,
                              void* d_out, int out_size)
{
    const float* logits = (const float*)d_in[0];   // tail_logits (B,T,V) f32
    const int*   tgt    = (const int*)  d_in[1];   // target_idx  (B,M) i32
    const float* phon   = (const float*)d_in[2];   // phon_cost   (V,V) f32
    float* out = (float*)d_out;
    const int B = out_size;                        // 8192

    cudaFuncSetAttribute(rhyme_dp_kernel,
                         cudaFuncAttributeMaxDynamicSharedMemorySize,
                         SMEM_BYTES);
    const int grid = (B + WARPS_PER_BLOCK - 1) / WARPS_PER_BLOCK;
    rhyme_dp_kernel<<<grid, THREADS_PER_BLOCK, SMEM_BYTES>>>(
        logits, tgt, phon, out, B);
}

// round 3
// speedup vs baseline: 2.1585x; 1.7088x over previous
#include <cuda_runtime.h>
#include <cuda_fp16.h>

// B=8192, T=16, M=16, V=256 fixed.
#define INS_DEL 10.0f
#define FIRST_CHAR_COST 10.0f

#define WARPS_PER_BLOCK 4
#define THREADS_PER_BLOCK (WARPS_PER_BLOCK * 32)

// Per-warp shared: P[t][v] half, row stride 264 halves (528B = 33*16B -> 
// ldmatrix conflict-free); S[t][m] fp32 stride 18 (wavefront conflict-free).
#define PSTR 264
#define P_BYTES (16 * PSTR * 2)            // 8448
#define SSTRIDE 18
#define S_BYTES (16 * SSTRIDE * 4)         // 1152
#define WARP_SMEM_BYTES (P_BYTES + S_BYTES)  // 9600
#define SMEM_BYTES (WARPS_PER_BLOCK * WARP_SMEM_BYTES)   // 38400

__device__ __forceinline__ void ldsm_x4(unsigned &r0, unsigned &r1,
                                        unsigned &r2, unsigned &r3,
                                        unsigned saddr) {
    asm volatile("ldmatrix.sync.aligned.m8n8.x4.shared.b16 {%0,%1,%2,%3}, [%4];\n"
                 : "=r"(r0), "=r"(r1), "=r"(r2), "=r"(r3) : "r"(saddr));
}

__device__ __forceinline__ void mma16816(float d[4],
                                         unsigned a0, unsigned a1,
                                         unsigned a2, unsigned a3,
                                         unsigned b0, unsigned b1) {
    asm volatile("mma.sync.aligned.m16n8k16.row.col.f32.f16.f16.f32 "
                 "{%0,%1,%2,%3}, {%4,%5,%6,%7}, {%8,%9}, {%0,%1,%2,%3};\n"
                 : "+f"(d[0]), "+f"(d[1]), "+f"(d[2]), "+f"(d[3])
                 : "r"(a0), "r"(a1), "r"(a2), "r"(a3), "r"(b0), "r"(b1));
}

__device__ __forceinline__ unsigned pack_h2(float x, float y) {
    __half2 h = __floats2half2_rn(x, y);
    return *(unsigned*)&h;
}

__global__ void __launch_bounds__(THREADS_PER_BLOCK, 6)
rhyme_dp_kernel(const float* __restrict__ logits,
                const int* __restrict__ tgt,
                const float* __restrict__ phon,
                float* __restrict__ out, int B)
{
    extern __shared__ char smem[];
    const int w    = threadIdx.x >> 5;
    const int lane = threadIdx.x & 31;
    const int b    = blockIdx.x * WARPS_PER_BLOCK + w;
    if (b >= B) return;

    __half* P = (__half*)(smem + w * WARP_SMEM_BYTES);
    float*  S = (float*)(smem + w * WARP_SMEM_BYTES + P_BYTES);

    const float* lg = logits + (size_t)b * (16 * 256);
    const int m = lane & 15;

    const int gm = tgt[b * 16 + m];
    const int g0 = __shfl_sync(0xffffffffu, gm, 0);

    // ---------------- Phase 1: softmax -> shared P (half, invZ folded) -----
    {
        const float4* rows = (const float4*)lg;   // 16 rows x 64 float4
        const int li = lane * 2;
        float4 xa0 = rows[li],        xa1 = rows[li + 1];
        float4 xb0 = rows[64 + li],   xb1 = rows[64 + li + 1];
#pragma unroll
        for (int t = 0; t < 16; ++t) {
            float4 x0 = xa0, x1 = xa1;
            xa0 = xb0; xa1 = xb1;
            if (t < 14) {
                xb0 = rows[(t + 2) * 64 + li];
                xb1 = rows[(t + 2) * 64 + li + 1];
            }
            float4 e0, e1;
            e0.x = __expf(x0.x); e0.y = __expf(x0.y);
            e0.z = __expf(x0.z); e0.w = __expf(x0.w);
            e1.x = __expf(x1.x); e1.y = __expf(x1.y);
            e1.z = __expf(x1.z); e1.w = __expf(x1.w);
            float s = (e0.x + e0.y) + (e0.z + e0.w)
                    + (e1.x + e1.y) + (e1.z + e1.w);
#pragma unroll
            for (int o = 16; o; o >>= 1)
                s += __shfl_xor_sync(0xffffffffu, s, o);
            const float iz = __fdividef(1.0f, s);

            unsigned h[4];
            h[0] = pack_h2(e0.x * iz, e0.y * iz);
            h[1] = pack_h2(e0.z * iz, e0.w * iz);
            h[2] = pack_h2(e1.x * iz, e1.y * iz);
            h[3] = pack_h2(e1.z * iz, e1.w * iz);
            *(uint4*)(P + t * PSTR + lane * 8) = *(uint4*)h;
        }
    }
    __syncwarp();

    // ---------------- Phase 2: sub = P @ C_gather via HMMA ------------------
    // A: P[t][v] (16x256 half, row-major) via ldmatrix from shared.
    // B: C_gather[v][m] = phon[v][g_m] = phon[g_m][v] (symmetric), built per
    //    lane straight from L2-resident phon rows.
    float d0[4] = {0.f, 0.f, 0.f, 0.f};
    float d1[4] = {0.f, 0.f, 0.f, 0.f};
    {
        // ldmatrix address: lane<16 -> row lane, col 0; lane>=16 -> row lane-15..., col 8
        unsigned pbase = (unsigned)__cvta_generic_to_shared(P);
        unsigned abase = pbase + (unsigned)((lane & 15) * (PSTR * 2) + (lane >> 4) * 16);

        // B fragment: n = lane>>2 (+8 for ntile1), k = (lane&3)*2 (+1, +8, +9)
        const int gn0 = __shfl_sync(0xffffffffu, gm, lane >> 2);
        const int gn1 = __shfl_sync(0xffffffffu, gm, 8 + (lane >> 2));
        const float* r0 = phon + (size_t)gn0 * 256 + (lane & 3) * 2;
        const float* r1 = phon + (size_t)gn1 * 256 + (lane & 3) * 2;

#pragma unroll
        for (int kt = 0; kt < 16; ++kt) {
            unsigned a0, a1, a2, a3;
            ldsm_x4(a0, a1, a2, a3, abase + kt * 32);

            float2 f00 = __ldg((const float2*)(r0 + kt * 16));
            float2 f01 = __ldg((const float2*)(r0 + kt * 16 + 8));
            float2 f10 = __ldg((const float2*)(r1 + kt * 16));
            float2 f11 = __ldg((const float2*)(r1 + kt * 16 + 8));

            mma16816(d0, a0, a1, a2, a3, pack_h2(f00.x, f00.y), pack_h2(f01.x, f01.y));
            mma16816(d1, a0, a1, a2, a3, pack_h2(f10.x, f10.y), pack_h2(f11.x, f11.y));
        }
    }

    // D fragment -> S[t][m]: c0,c1 at (t=lane>>2, m=(lane&3)*2), c2,c3 at t+8
    {
        const int tq = lane >> 2;
        const int mc = (lane & 3) * 2;
        *(float2*)(S + tq * SSTRIDE + mc)           = make_float2(d0[0], d0[1]);
        *(float2*)(S + (tq + 8) * SSTRIDE + mc)     = make_float2(d0[2], d0[3]);
        *(float2*)(S + tq * SSTRIDE + mc + 8)       = make_float2(d1[0], d1[1]);
        *(float2*)(S + (tq + 8) * SSTRIDE + mc + 8) = make_float2(d1[2], d1[3]);
    }
    __syncwarp();

    // ---------------- Phase 3: soft-DP wavefront (lane = column j-1) --------
    float cur = 0.0f, prev = 0.0f;
#pragma unroll
    for (int s = 0; s <= 30; ++s) {
        float leftv = __shfl_up_sync(0xffffffffu, cur, 1);
        float diagv = __shfl_up_sync(0xffffffffu, prev, 1);
        const int i = s - m + 1;
        const bool active = (i >= 1) && (i <= 16);

        float up;
        if (i == 1) {                 // row above is DP row 0: 10*j
            up    = INS_DEL * (float)(m + 1);
            diagv = INS_DEL * (float)m;
        } else {
            up = cur;
        }
        if (m == 0) {                 // column left is DP col 0: 10*i
            leftv = INS_DEL * (float)i;
            diagv = INS_DEL * (float)(i - 1);
        }

        const int si = active ? (s - m) : 0;
        const float sc = S[si * SSTRIDE + m];

        const float a  = up    + INS_DEL;
        const float bb = leftv + INS_DEL;
        const float c  = diagv + sc;
        const float mn = fminf(a, fminf(bb, c));
        const float r  = __expf(mn - a) + __expf(mn - bb) + __expf(mn - c);
        const float val = mn - __logf(r);

        if (active) { prev = cur; cur = val; }
    }

    // ---------------- Phase 4: first-char term + output ---------------------
    if (lane == 15) {
        const float fm = __half2float(P[g0]);     // p[b,0,tgt[b,0]] (row 0)
        out[b] = cur + FIRST_CHAR_COST * (1.0f - fm);
    }
}

extern "C" void kernel_launch(void* const* d_in, const int* in_sizes, int n_in,
                              void* d_out, int out_size)
{
    const float* logits = (const float*)d_in[0];   // tail_logits (B,T,V) f32
    const int*   tgt    = (const int*)  d_in[1];   // target_idx  (B,M) i32
    const float* phon   = (const float*)d_in[2];   // phon_cost   (V,V) f32
    float* out = (float*)d_out;
    const int B = out_size;                        // 8192

    cudaFuncSetAttribute(rhyme_dp_kernel,
                         cudaFuncAttributeMaxDynamicSharedMemorySize,
                         SMEM_BYTES);
    const int grid = (B + WARPS_PER_BLOCK - 1) / WARPS_PER_BLOCK;
    rhyme_dp_kernel<<<grid, THREADS_PER_BLOCK, SMEM_BYTES>>>(
        logits, tgt, phon, out, B);
}

// round 4
// speedup vs baseline: 2.3929x; 1.1086x over previous
#include <cuda_runtime.h>
#include <cuda_fp16.h>

// B=8192, T=16, M=16, V=256 fixed.
#define INS_DEL 10.0f
#define FIRST_CHAR_COST 10.0f

#define WARPS_PER_BLOCK 4
#define THREADS_PER_BLOCK (WARPS_PER_BLOCK * 32)

// Per-warp shared: E[t][v] half (raw exp), row stride 264 halves (528B = 33
// granules -> ldmatrix conflict-free); S[t][m] fp32 stride 18.
#define PSTR 264
#define P_BYTES (16 * PSTR * 2)              // 8448
#define SSTRIDE 18
#define S_BYTES (16 * SSTRIDE * 4)           // 1152
#define WARP_SMEM_BYTES (P_BYTES + S_BYTES)  // 9600
#define SMEM_BYTES (WARPS_PER_BLOCK * WARP_SMEM_BYTES)

__device__ __forceinline__ void ldsm_x4(unsigned &r0, unsigned &r1,
                                        unsigned &r2, unsigned &r3,
                                        unsigned saddr) {
    asm volatile("ldmatrix.sync.aligned.m8n8.x4.shared.b16 {%0,%1,%2,%3}, [%4];\n"
                 : "=r"(r0), "=r"(r1), "=r"(r2), "=r"(r3) : "r"(saddr));
}

__device__ __forceinline__ void mma16816(float d[4],
                                         unsigned a0, unsigned a1,
                                         unsigned a2, unsigned a3,
                                         unsigned b0, unsigned b1) {
    asm volatile("mma.sync.aligned.m16n8k16.row.col.f32.f16.f16.f32 "
                 "{%0,%1,%2,%3}, {%4,%5,%6,%7}, {%8,%9}, {%0,%1,%2,%3};\n"
                 : "+f"(d[0]), "+f"(d[1]), "+f"(d[2]), "+f"(d[3])
                 : "r"(a0), "r"(a1), "r"(a2), "r"(a3), "r"(b0), "r"(b1));
}

__device__ __forceinline__ unsigned pack_h2(float x, float y) {
    __half2 h = __floats2half2_rn(x, y);
    return *(unsigned*)&h;
}

__global__ void __launch_bounds__(THREADS_PER_BLOCK, 5)
rhyme_dp_kernel(const float* __restrict__ logits,
                const int* __restrict__ tgt,
                const float* __restrict__ phon,
                float* __restrict__ out, int B)
{
    extern __shared__ char smem[];
    const int w    = threadIdx.x >> 5;
    const int lane = threadIdx.x & 31;
    const int b    = blockIdx.x * WARPS_PER_BLOCK + w;
    if (b >= B) return;

    __half* E = (__half*)(smem + w * WARP_SMEM_BYTES);
    float*  S = (float*)(smem + w * WARP_SMEM_BYTES + P_BYTES);

    const float* lg = logits + (size_t)b * (16 * 256);
    const int m = lane & 15;

    const int gm = tgt[b * 16 + m];
    const int g0 = __shfl_sync(0xffffffffu, gm, 0);

    // -------- Phase 1: raw exp -> shared E (half). NO reduction, no shfl. ---
    {
        const float4* rows = (const float4*)lg;   // 16 rows x 64 float4
        const int li = lane * 2;
#pragma unroll
        for (int t = 0; t < 16; ++t) {
            float4 x0 = rows[t * 64 + li];
            float4 x1 = rows[t * 64 + li + 1];
            unsigned h[4];
            h[0] = pack_h2(__expf(x0.x), __expf(x0.y));
            h[1] = pack_h2(__expf(x0.z), __expf(x0.w));
            h[2] = pack_h2(__expf(x1.x), __expf(x1.y));
            h[3] = pack_h2(__expf(x1.z), __expf(x1.w));
            *(uint4*)(E + t * PSTR + lane * 8) = *(uint4*)h;
        }
    }
    __syncwarp();

    // -------- Phase 2: [sub_raw | Z] = E @ [C_gather | ones] via HMMA -------
    // A: E[t][v] (16x256 half) via ldmatrix. B tiles 0,1: C[v][g_m] =
    // phon[g_m][v] (symmetric, contiguous rows, L2-resident). B tile 2:
    // constant ones column -> D2 col 0 = Z[t].
    float d0[4] = {0.f, 0.f, 0.f, 0.f};
    float d1[4] = {0.f, 0.f, 0.f, 0.f};
    float d2[4] = {0.f, 0.f, 0.f, 0.f};
    {
        unsigned pbase = (unsigned)__cvta_generic_to_shared(E);
        unsigned abase = pbase + (unsigned)((lane & 15) * (PSTR * 2) + (lane >> 4) * 16);

        const int gn0 = __shfl_sync(0xffffffffu, gm, lane >> 2);
        const int gn1 = __shfl_sync(0xffffffffu, gm, 8 + (lane >> 2));
        const float* r0 = phon + (size_t)gn0 * 256 + (lane & 3) * 2;
        const float* r1 = phon + (size_t)gn1 * 256 + (lane & 3) * 2;

        // ones-column B fragment: col n=0 -> lanes 0..3 hold 1.0 pairs
        const unsigned bone = (lane < 4) ? pack_h2(1.0f, 1.0f) : 0u;

#pragma unroll
        for (int kt = 0; kt < 16; ++kt) {
            unsigned a0, a1, a2, a3;
            ldsm_x4(a0, a1, a2, a3, abase + kt * 32);

            float2 f00 = __ldg((const float2*)(r0 + kt * 16));
            float2 f01 = __ldg((const float2*)(r0 + kt * 16 + 8));
            float2 f10 = __ldg((const float2*)(r1 + kt * 16));
            float2 f11 = __ldg((const float2*)(r1 + kt * 16 + 8));

            mma16816(d0, a0, a1, a2, a3, pack_h2(f00.x, f00.y), pack_h2(f01.x, f01.y));
            mma16816(d1, a0, a1, a2, a3, pack_h2(f10.x, f10.y), pack_h2(f11.x, f11.y));
            mma16816(d2, a0, a1, a2, a3, bone, bone);
        }
    }

    // -------- writeback: S[t][m] = sub_raw / Z[t] ---------------------------
    float z0_lane0;
    {
        // Z for row tq is in lane (lane & ~3): c0 (rows 0..7), c2 (rows 8..15)
        const float zlo = __shfl_sync(0xffffffffu, d2[0], lane & ~3);
        const float zhi = __shfl_sync(0xffffffffu, d2[2], lane & ~3);
        z0_lane0 = __shfl_sync(0xffffffffu, d2[0], 0);   // Z[0]
        const float rzlo = __fdividef(1.0f, zlo);
        const float rzhi = __fdividef(1.0f, zhi);

        const int tq = lane >> 2;
        const int mc = (lane & 3) * 2;
        *(float2*)(S + tq * SSTRIDE + mc)           = make_float2(d0[0] * rzlo, d0[1] * rzlo);
        *(float2*)(S + (tq + 8) * SSTRIDE + mc)     = make_float2(d0[2] * rzhi, d0[3] * rzhi);
        *(float2*)(S + tq * SSTRIDE + mc + 8)       = make_float2(d1[0] * rzlo, d1[1] * rzlo);
        *(float2*)(S + (tq + 8) * SSTRIDE + mc + 8) = make_float2(d1[2] * rzhi, d1[3] * rzhi);
    }
    __syncwarp();

    // -------- Phase 3: soft-DP wavefront (lane = column j-1) ----------------
    float cur = 0.0f, prev = 0.0f;
#pragma unroll
    for (int s = 0; s <= 30; ++s) {
        float leftv = __shfl_up_sync(0xffffffffu, cur, 1);
        float diagv = __shfl_up_sync(0xffffffffu, prev, 1);
        const int i = s - m + 1;
        const bool active = (i >= 1) && (i <= 16);

        float up;
        if (i == 1) {                 // row above is DP row 0: 10*j
            up    = INS_DEL * (float)(m + 1);
            diagv = INS_DEL * (float)m;
        } else {
            up = cur;
        }
        if (m == 0) {                 // column left is DP col 0: 10*i
            leftv = INS_DEL * (float)i;
            diagv = INS_DEL * (float)(i - 1);
        }

        const int si = active ? (s - m) : 0;
        const float sc = S[si * SSTRIDE + m];

        const float a  = up    + INS_DEL;
        const float bb = leftv + INS_DEL;
        const float c  = diagv + sc;
        const float mn = fminf(a, fminf(bb, c));
        const float r  = __expf(mn - a) + __expf(mn - bb) + __expf(mn - c);
        const float val = mn - __logf(r);

        if (active) { prev = cur; cur = val; }
    }

    // -------- Phase 4: first-char term + output -----------------------------
    if (lane == 15) {
        const float fm = __half2float(E[g0]) * __fdividef(1.0f, z0_lane0);
        out[b] = cur + FIRST_CHAR_COST * (1.0f - fm);
    }
}

extern "C" void kernel_launch(void* const* d_in, const int* in_sizes, int n_in,
                              void* d_out, int out_size)
{
    const float* logits = (const float*)d_in[0];   // tail_logits (B,T,V) f32
    const int*   tgt    = (const int*)  d_in[1];   // target_idx  (B,M) i32
    const float* phon   = (const float*)d_in[2];   // phon_cost   (V,V) f32
    float* out = (float*)d_out;
    const int B = out_size;                        // 8192

    cudaFuncSetAttribute(rhyme_dp_kernel,
                         cudaFuncAttributeMaxDynamicSharedMemorySize,
                         SMEM_BYTES);
    const int grid = (B + WARPS_PER_BLOCK - 1) / WARPS_PER_BLOCK;
    rhyme_dp_kernel<<<grid, THREADS_PER_BLOCK, SMEM_BYTES>>>(
        logits, tgt, phon, out, B);
}